// round 8
// baseline (speedup 1.0000x reference)
#include <cuda_runtime.h>
#include <cstdint>

#define Bdim 4
#define Tdim 256
#define Sdim 256
#define Ddim 512

// Scratch (allocation-free rule: __device__ globals)
__device__ float g_wq[Bdim * Tdim * Ddim];    // 2 MB
__device__ float g_uh[Bdim * Sdim * Ddim];    // 2 MB
__device__ float g_sc[Bdim * Tdim * Sdim];    // 1 MB (compacted scores, then full attn)
__device__ float g_pre1[Bdim * Sdim * Ddim];  // 2 MB  ctx @ Wout_top
__device__ float g_pre2[Bdim * Tdim * Ddim];  // 2 MB  output @ Wout_bot + bout
__device__ int   g_sidx[Bdim * Sdim];         // compacted unmasked column idx
__device__ int   g_nu[Bdim];                  // count of unmasked per batch

__device__ __forceinline__ float tanh_fast(float x) {
    float y;
    asm("tanh.approx.f32 %0, %1;" : "=f"(y) : "f"(x));
    return y;
}

__device__ __forceinline__ uint32_t f2tf32(float x) {
    uint32_t y;
    asm("cvt.rna.tf32.f32 %0, %1;" : "=r"(y) : "f"(x));
    return y;
}

__device__ __forceinline__ void mma_tf32(float* d, const uint32_t* a,
                                         const uint32_t* b) {
    asm volatile(
        "mma.sync.aligned.m16n8k8.row.col.f32.tf32.tf32.f32 "
        "{%0,%1,%2,%3}, {%4,%5,%6,%7}, {%8,%9}, {%0,%1,%2,%3};"
        : "+f"(d[0]), "+f"(d[1]), "+f"(d[2]), "+f"(d[3])
        : "r"(a[0]), "r"(a[1]), "r"(a[2]), "r"(a[3]), "r"(b[0]), "r"(b[1]));
}

#define CP16(dst, src) \
    asm volatile("cp.async.cg.shared.global [%0], [%1], 16;" \
                 :: "r"(dst), "l"(src) : "memory")
#define CP_COMMIT() asm volatile("cp.async.commit_group;" ::: "memory")
#define CP_WAIT2()  asm volatile("cp.async.wait_group 2;" ::: "memory")

#define STAGES 4
#define LDA 20
#define LDB 72
#define ABYTES (64 * LDA * 4)
#define BBYTES (16 * LDB * 4)

// ---------------------------------------------------------------------------
// 128-thread core: 64x64 tile, 4 warps (2x2), warp tile 32x32.
// ---------------------------------------------------------------------------
__device__ __forceinline__ void gemm_core(
    const float* __restrict__ A, int lda,
    const float* __restrict__ B, int ldb, int K,
    const float* __restrict__ bias, float* __restrict__ C, int N,
    int m0, int n0)
{
    __shared__ float As[STAGES][64 * LDA];
    __shared__ float Bs[STAGES][16 * LDB];

    const int tid = threadIdx.x;
    const int wid = tid >> 5;
    const int lane = tid & 31;
    const int g = lane >> 2;
    const int tig = lane & 3;
    const int warp_m = wid >> 1;
    const int warp_n = wid & 1;

    const int ar = tid >> 1;
    const int ak = (tid & 1) << 3;
    const int br = tid >> 3;
    const int bc = (tid & 7) << 3;

    uint32_t as_s = (uint32_t)__cvta_generic_to_shared(&As[0][0]);
    uint32_t bs_s = (uint32_t)__cvta_generic_to_shared(&Bs[0][0]);

    const int NT = K >> 4;

    float acc[2][4][4];
#pragma unroll
    for (int i = 0; i < 2; i++)
#pragma unroll
        for (int j = 0; j < 4; j++)
#pragma unroll
            for (int q = 0; q < 4; q++) acc[i][j][q] = 0.f;

    auto issue = [&](int stage, int kt) {
        const int kg = kt << 4;
        const float* s0 = A + (long)(m0 + ar) * lda + kg + ak;
        uint32_t d0 = as_s + stage * ABYTES + (ar * LDA + ak) * 4;
        CP16(d0, s0);
        CP16(d0 + 16, s0 + 4);
        const float* sb = B + (long)(kg + br) * ldb + n0 + bc;
        uint32_t db = bs_s + stage * BBYTES + (br * LDB + bc) * 4;
        CP16(db, sb);
        CP16(db + 16, sb + 4);
    };

#pragma unroll
    for (int p = 0; p < STAGES - 1; p++) {
        if (p < NT) issue(p, p);
        CP_COMMIT();
    }

    for (int t = 0; t < NT; t++) {
        const int st = t & (STAGES - 1);
        CP_WAIT2();
        __syncthreads();

        if (t + STAGES - 1 < NT) issue((t + STAGES - 1) & (STAGES - 1), t + STAGES - 1);
        CP_COMMIT();

        const float* as = As[st];
        const float* bs = Bs[st];
        const int mb = warp_m * 32;
        const int nb = warp_n * 32;
#pragma unroll
        for (int ks = 0; ks < 2; ks++) {
            const int k0 = ks << 3;
            uint32_t a[2][4], b[4][2];
#pragma unroll
            for (int im = 0; im < 2; im++) {
                const float* ap = as + (mb + im * 16 + g) * LDA;
                a[im][0] = f2tf32(ap[k0 + tig]);
                a[im][1] = f2tf32(ap[8 * LDA + k0 + tig]);
                a[im][2] = f2tf32(ap[k0 + tig + 4]);
                a[im][3] = f2tf32(ap[8 * LDA + k0 + tig + 4]);
            }
#pragma unroll
            for (int in = 0; in < 4; in++) {
                const int nc = nb + in * 8 + g;
                b[in][0] = f2tf32(bs[(k0 + tig) * LDB + nc]);
                b[in][1] = f2tf32(bs[(k0 + tig + 4) * LDB + nc]);
            }
#pragma unroll
            for (int im = 0; im < 2; im++)
#pragma unroll
                for (int in = 0; in < 4; in++)
                    mma_tf32(acc[im][in], a[im], b[in]);
        }
        __syncthreads();
    }

    const int mb = warp_m * 32;
    const int nb = warp_n * 32;
#pragma unroll
    for (int im = 0; im < 2; im++) {
#pragma unroll
        for (int in = 0; in < 4; in++) {
            const int row = m0 + mb + im * 16 + g;
            const int col = n0 + nb + in * 8 + tig * 2;
            float bx = 0.f, by = 0.f;
            if (bias) { bx = bias[col]; by = bias[col + 1]; }
            float2 o0 = make_float2(acc[im][in][0] + bx, acc[im][in][1] + by);
            float2 o1 = make_float2(acc[im][in][2] + bx, acc[im][in][3] + by);
            *(float2*)&C[(long)row * N + col] = o0;
            *(float2*)&C[(long)(row + 8) * N + col] = o1;
        }
    }
}

// ---------------------------------------------------------------------------
// 256-thread core: 64x64 tile, 8 warps (2m x 4n), warp tile 32x16. (gemm_fin)
// ---------------------------------------------------------------------------
__device__ __forceinline__ void gemm_core_256(
    const float* __restrict__ A, int lda,
    const float* __restrict__ B, int ldb, int K,
    const float* __restrict__ addend,
    float* __restrict__ C, int N, int m0, int n0)
{
    __shared__ float As[STAGES][64 * LDA];
    __shared__ float Bs[STAGES][16 * LDB];

    const int tid = threadIdx.x;
    const int wid = tid >> 5;
    const int lane = tid & 31;
    const int g = lane >> 2;
    const int tig = lane & 3;
    const int warp_m = wid >> 2;
    const int warp_n = wid & 3;

    const int ar = tid >> 2;
    const int ak = (tid & 3) << 2;
    const int br = tid >> 4;
    const int bc = (tid & 15) << 2;

    uint32_t as_s = (uint32_t)__cvta_generic_to_shared(&As[0][0]);
    uint32_t bs_s = (uint32_t)__cvta_generic_to_shared(&Bs[0][0]);

    const int NT = K >> 4;

    float acc[2][2][4];
#pragma unroll
    for (int i = 0; i < 2; i++)
#pragma unroll
        for (int j = 0; j < 2; j++)
#pragma unroll
            for (int q = 0; q < 4; q++) acc[i][j][q] = 0.f;

    auto issue = [&](int stage, int kt) {
        const int kg = kt << 4;
        const float* s0 = A + (long)(m0 + ar) * lda + kg + ak;
        uint32_t d0 = as_s + stage * ABYTES + (ar * LDA + ak) * 4;
        CP16(d0, s0);
        const float* sb = B + (long)(kg + br) * ldb + n0 + bc;
        uint32_t db = bs_s + stage * BBYTES + (br * LDB + bc) * 4;
        CP16(db, sb);
    };

#pragma unroll
    for (int p = 0; p < STAGES - 1; p++) {
        if (p < NT) issue(p, p);
        CP_COMMIT();
    }

    for (int t = 0; t < NT; t++) {
        const int st = t & (STAGES - 1);
        CP_WAIT2();
        __syncthreads();

        if (t + STAGES - 1 < NT) issue((t + STAGES - 1) & (STAGES - 1), t + STAGES - 1);
        CP_COMMIT();

        const float* as = As[st];
        const float* bs = Bs[st];
        const int mb = warp_m * 32;
        const int nb = warp_n * 16;
#pragma unroll
        for (int ks = 0; ks < 2; ks++) {
            const int k0 = ks << 3;
            uint32_t a[2][4], b[2][2];
#pragma unroll
            for (int im = 0; im < 2; im++) {
                const float* ap = as + (mb + im * 16 + g) * LDA;
                a[im][0] = f2tf32(ap[k0 + tig]);
                a[im][1] = f2tf32(ap[8 * LDA + k0 + tig]);
                a[im][2] = f2tf32(ap[k0 + tig + 4]);
                a[im][3] = f2tf32(ap[8 * LDA + k0 + tig + 4]);
            }
#pragma unroll
            for (int in = 0; in < 2; in++) {
                const int nc = nb + in * 8 + g;
                b[in][0] = f2tf32(bs[(k0 + tig) * LDB + nc]);
                b[in][1] = f2tf32(bs[(k0 + tig + 4) * LDB + nc]);
            }
#pragma unroll
            for (int im = 0; im < 2; im++)
#pragma unroll
                for (int in = 0; in < 2; in++)
                    mma_tf32(acc[im][in], a[im], b[in]);
        }
        __syncthreads();
    }

    const int mb = warp_m * 32;
    const int nb = warp_n * 16;
#pragma unroll
    for (int im = 0; im < 2; im++) {
#pragma unroll
        for (int in = 0; in < 2; in++) {
            const int row = m0 + mb + im * 16 + g;
            const int col = n0 + nb + in * 8 + tig * 2;
            float2 o0 = make_float2(acc[im][in][0], acc[im][in][1]);
            float2 o1 = make_float2(acc[im][in][2], acc[im][in][3]);
            if (addend) {
                const float2 r0 = *(const float2*)&addend[(long)row * N + col];
                const float2 r1 = *(const float2*)&addend[(long)(row + 8) * N + col];
                o0.x += r0.x; o0.y += r0.y;
                o1.x += r1.x; o1.y += r1.y;
            }
            *(float2*)&C[(long)row * N + col] = o0;
            *(float2*)&C[(long)(row + 8) * N + col] = o1;
        }
    }
}

// Four independent 1024x512x512 jobs selected by blockIdx.z
struct Job {
    const float* A;
    const float* B;
    const float* bias;
    float* C;
};

__global__ __launch_bounds__(128) void gemm4(Job j0, Job j1, Job j2, Job j3)
{
    Job j = (blockIdx.z == 0) ? j0 : (blockIdx.z == 1) ? j1
          : (blockIdx.z == 2) ? j2 : j3;
    gemm_core(j.A, Ddim, j.B, Ddim, Ddim, j.bias, j.C, Ddim,
              blockIdx.y * 64, blockIdx.x * 64);
}

// Final: out[b] = attn[b] @ pre1[b] + pre2[b]   (256 x 512, K=256 per batch)
__global__ __launch_bounds__(256) void gemm_fin(
    const float* __restrict__ attn, const float* __restrict__ pre1,
    const float* __restrict__ pre2, float* __restrict__ out)
{
    const int z = blockIdx.z;
    gemm_core_256(attn + (long)z * Tdim * Sdim, Sdim,
                  pre1 + (long)z * Sdim * Ddim, Ddim, Sdim,
                  pre2 + (long)z * Tdim * Ddim,
                  out + (long)z * Tdim * Ddim, Ddim,
                  blockIdx.y * 64, blockIdx.x * 64);
}

// ---------------------------------------------------------------------------
// Compact unmasked column indices per batch. One block per batch.
// ---------------------------------------------------------------------------
__global__ __launch_bounds__(256) void compact_kernel(
    const int* __restrict__ mask, int* __restrict__ sidx, int* __restrict__ nu)
{
    __shared__ int wsum[8];
    __shared__ int woff[8];

    const int b = blockIdx.x;
    const int tid = threadIdx.x;
    const int lane = tid & 31, warp = tid >> 5;

    const int keep = 1 - mask[b * Sdim + tid];
    const unsigned bal = __ballot_sync(0xffffffffu, keep);
    const int pre = __popc(bal & ((1u << lane) - 1u));
    if (lane == 0) wsum[warp] = __popc(bal);
    __syncthreads();
    if (tid == 0) {
        int acc = 0;
        for (int w = 0; w < 8; w++) { woff[w] = acc; acc += wsum[w]; }
        nu[b] = acc;
    }
    __syncthreads();
    if (keep) sidx[b * Sdim + woff[warp] + pre] = tid;
    __syncthreads();
    const int n = woff[7] + wsum[7];
    for (int j = n + tid; j < Sdim; j += 256) sidx[b * Sdim + j] = 0;
}

// ---------------------------------------------------------------------------
// score[b,t,j] = sum_d v[d] * tanh(wq[b,t,d] + uh[b,sidx[j],d])  (compacted)
// Only columns j < nU[b] are computed (MUFU work ~halved by masking).
// ---------------------------------------------------------------------------
__global__ __launch_bounds__(256) void score_kernel(
    const float* __restrict__ wq, const float* __restrict__ uh,
    const float* __restrict__ v, float* __restrict__ sc,
    const int* __restrict__ sidx, const int* __restrict__ nu)
{
    __shared__ float Aq[32][33];
    __shared__ float Au[32][33];
    __shared__ float vs[32];
    __shared__ int cidx[32];

    const int b = blockIdx.z;
    const int t0 = blockIdx.y * 32;
    const int s0 = blockIdx.x * 32;

    const int nU = nu[b];
    if (s0 >= nU) return;

    const int tid = threadIdx.x;
    const int tx = tid & 15, ty = tid >> 4;

    if (tid < 32) cidx[tid] = sidx[b * Sdim + s0 + tid];  // padded with 0 past nU
    __syncthreads();

    const float* wqb = wq + ((long)b * Tdim + t0) * Ddim;
    const float* uhb = uh + (long)b * Sdim * Ddim;

    const int lr = tid >> 3;
    const int lc = (tid & 7) << 2;
    const long urow = (long)cidx[lr] * Ddim;

    float acc00 = 0.f, acc01 = 0.f, acc10 = 0.f, acc11 = 0.f;

    for (int d0 = 0; d0 < Ddim; d0 += 32) {
        float4 q = *(const float4*)&wqb[(long)lr * Ddim + d0 + lc];
        Aq[lc + 0][lr] = q.x;
        Aq[lc + 1][lr] = q.y;
        Aq[lc + 2][lr] = q.z;
        Aq[lc + 3][lr] = q.w;
        float4 u = *(const float4*)&uhb[urow + d0 + lc];
        Au[lc + 0][lr] = u.x;
        Au[lc + 1][lr] = u.y;
        Au[lc + 2][lr] = u.z;
        Au[lc + 3][lr] = u.w;
        if (tid < 32) vs[tid] = v[d0 + tid];
        __syncthreads();

#pragma unroll
        for (int dk = 0; dk < 32; dk++) {
            float vv = vs[dk];
            float a0 = Aq[dk][ty * 2 + 0];
            float a1 = Aq[dk][ty * 2 + 1];
            float u0 = Au[dk][tx * 2 + 0];
            float u1 = Au[dk][tx * 2 + 1];
            acc00 += vv * tanh_fast(a0 + u0);
            acc01 += vv * tanh_fast(a0 + u1);
            acc10 += vv * tanh_fast(a1 + u0);
            acc11 += vv * tanh_fast(a1 + u1);
        }
        __syncthreads();
    }

    float* scp = sc + ((long)b * Tdim + t0) * Sdim + s0;
    scp[(long)(ty * 2 + 0) * Sdim + tx * 2 + 0] = acc00;
    scp[(long)(ty * 2 + 0) * Sdim + tx * 2 + 1] = acc01;
    scp[(long)(ty * 2 + 1) * Sdim + tx * 2 + 0] = acc10;
    scp[(long)(ty * 2 + 1) * Sdim + tx * 2 + 1] = acc11;
}

// ---------------------------------------------------------------------------
// Softmax over compacted columns, then zero+scatter into full attn layout.
// Masked entries are exactly 0 (matches reference); max over unmasked only
// (cancels exactly in the normalized result).
// ---------------------------------------------------------------------------
__global__ __launch_bounds__(256) void softmax_kernel(
    float* __restrict__ sc, const int* __restrict__ sidx,
    const int* __restrict__ nu, float* __restrict__ attn_out)
{
    const int warp = threadIdx.x >> 5;
    const int lane = threadIdx.x & 31;
    const int row = blockIdx.x * 8 + warp;   // b*T + t
    const int b = row >> 8;
    const int nU = nu[b];

    float* rp = sc + (long)row * Sdim;
    const int* ip = sidx + b * Sdim;

    float x[8];
    float m = -1e30f;
#pragma unroll
    for (int i = 0; i < 8; i++) {
        x[i] = rp[i * 32 + lane];
        if (i * 32 + lane < nU) m = fmaxf(m, x[i]);
    }
#pragma unroll
    for (int o = 16; o > 0; o >>= 1)
        m = fmaxf(m, __shfl_xor_sync(0xffffffffu, m, o));

    float e[8];
    float sum = 0.f;
#pragma unroll
    for (int i = 0; i < 8; i++) {
        e[i] = (i * 32 + lane < nU) ? __expf(x[i] - m) : 0.f;
        sum += e[i];
    }
#pragma unroll
    for (int o = 16; o > 0; o >>= 1)
        sum += __shfl_xor_sync(0xffffffffu, sum, o);

    const float inv = 1.0f / sum;
    float* ap = attn_out ? attn_out + (long)row * Sdim : nullptr;

    // zero full row, then scatter compacted values
#pragma unroll
    for (int i = 0; i < 8; i++) {
        rp[i * 32 + lane] = 0.f;
        if (ap) ap[i * 32 + lane] = 0.f;
    }
    __syncwarp();
#pragma unroll
    for (int i = 0; i < 8; i++) {
        const int j = i * 32 + lane;
        if (j < nU) {
            const int s = ip[j];
            const float a = e[i] * inv;
            rp[s] = a;
            if (ap) ap[s] = a;
        }
    }
}

// ---------------------------------------------------------------------------
extern "C" void kernel_launch(void* const* d_in, const int* in_sizes, int n_in,
                              void* d_out, int out_size)
{
    const float* out_in = (const float*)d_in[0];  // (B,T,D)
    const float* ctx    = (const float*)d_in[1];  // (B,S,D)
    const int*   mask   = (const int*)d_in[2];    // (B,S)
    const float* Wq     = (const float*)d_in[3];  // (D,D)
    const float* bq     = (const float*)d_in[4];  // (D,)
    const float* Wc     = (const float*)d_in[5];  // (D,D)
    const float* v      = (const float*)d_in[6];  // (D,)
    const float* Wout   = (const float*)d_in[7];  // (2D,D)
    const float* bout   = (const float*)d_in[8];  // (D,)

    float *p_wq, *p_uh, *p_sc, *p_pre1, *p_pre2;
    int *p_sidx, *p_nu;
    cudaGetSymbolAddress((void**)&p_wq, g_wq);
    cudaGetSymbolAddress((void**)&p_uh, g_uh);
    cudaGetSymbolAddress((void**)&p_sc, g_sc);
    cudaGetSymbolAddress((void**)&p_pre1, g_pre1);
    cudaGetSymbolAddress((void**)&p_pre2, g_pre2);
    cudaGetSymbolAddress((void**)&p_sidx, g_sidx);
    cudaGetSymbolAddress((void**)&p_nu, g_nu);

    const long BTD = (long)Bdim * Tdim * Ddim;  // 524288
    const long BTS = (long)Bdim * Tdim * Sdim;  // 262144
    float* out_f = (float*)d_out;
    float* attn_out = ((long)out_size >= BTD + BTS) ? (out_f + BTD) : nullptr;

    // 0) compact unmasked columns (tiny)
    compact_kernel<<<Bdim, 256>>>(mask, p_sidx, p_nu);

    // 1) Four fused 1024x512x512 GEMMs
    Job j0{out_in, Wq, bq, p_wq};
    Job j1{ctx, Wc, nullptr, p_uh};
    Job j2{ctx, Wout, nullptr, p_pre1};
    Job j3{out_in, Wout + (long)Ddim * Ddim, bout, p_pre2};
    gemm4<<<dim3(Ddim / 64, (Bdim * Tdim) / 64, 4), 128>>>(j0, j1, j2, j3);

    // 2) score on compacted columns only (~half the tanh work)
    score_kernel<<<dim3(Sdim / 32, Tdim / 32, Bdim), 256>>>(
        p_wq, p_uh, v, p_sc, p_sidx, p_nu);

    // 3) softmax over compacted + scatter to full attn layout
    softmax_kernel<<<(Bdim * Tdim) / 8, 256>>>(p_sc, p_sidx, p_nu, attn_out);

    // 4) out = attn @ pre1 + pre2   (batched 256x512, K=256)
    gemm_fin<<<dim3(Ddim / 64, Tdim / 64, Bdim), 256>>>(p_sc, p_pre1, p_pre2, out_f);
}